// round 16
// baseline (speedup 1.0000x reference)
#include <cuda_runtime.h>

#define NB 2
#define NA 100000
#define NC 80
#define NCLS 79          // classes excluding background (class 0)
#define KPERF 500
#define KPROP 100
#define NTASK (NB*NCLS)  // 158
#define SCORE_THR 0.05f
#define THR0 0.992f      // static candidate threshold (self-checked; fallback if violated)
#define NSH 4            // counter shards
#define SCAP 512         // per-shard capacity
#define CAP 2048
#define APB 128          // anchors per full collect block (128*20 = 2560 f4 = 512 thr * 5)
#define NFULL (NA/APB)   // 781 full blocks; tail 32 anchors
#define NBLK (NFULL + 1)
#define SBUFC 320        // per-block smem candidate buffer (expected ~81, +26 sigma)
#define RPRE 256         // NMS prefix rows (exactness certified at runtime)
#define KEEPC 128        // kept entries per class forwarded to final
#define MFIN (NCLS*KEEPC)   // 10112
#define RPT 20           // ceil(MFIN/512)

typedef unsigned long long u64;
typedef unsigned int u32;

// ---- scratch (static device arrays; allocation-free) ----
__device__ int    g_cnt[NTASK*NSH];
__device__ u64    g_cand[(size_t)NTASK*NSH*SCAP];   // 2.6 MB
__device__ float  g_fval[NTASK*KEEPC];
__device__ int    g_fflat[NTASK*KEEPC];
__device__ int    g_faidx[NTASK*KEEPC];

__device__ __forceinline__ u32 fmono(float f){
    u32 u = __float_as_uint(f);
    return (u & 0x80000000u) ? ~u : (u | 0x80000000u);
}
__device__ __forceinline__ float fmono_inv(u32 k){
    return __uint_as_float((k & 0x80000000u) ? (k & 0x7FFFFFFFu) : ~k);
}

// mmdet delta decode + clip to [0,1]
__device__ __forceinline__ float4 decode_box(float4 d, float4 an){
    const float MAXR = 4.135166556742356f;   // |ln(16/1000)|
    float dw = fminf(fmaxf(d.z, -MAXR), MAXR);
    float dh = fminf(fmaxf(d.w, -MAXR), MAXR);
    float pw = an.z - an.x, ph = an.w - an.y;
    float px = (an.x + an.z)*0.5f, py = (an.y + an.w)*0.5f;
    float gw = pw*expf(dw), gh = ph*expf(dh);
    float gx = px + pw*d.x, gy = py + ph*d.y;
    float4 o;
    o.x = fminf(fmaxf(gx - gw*0.5f, 0.f), 1.f);
    o.y = fminf(fmaxf(gy - gh*0.5f, 0.f), 1.f);
    o.z = fminf(fmaxf(gx + gw*0.5f, 0.f), 1.f);
    o.w = fminf(fmaxf(gy + gh*0.5f, 0.f), 1.f);
    return o;
}

// ================================================================ collect: smem-batched candidates > THR0
// Hot loop: load + compare + smem atomic only. Global atomics/stores deferred
// to a single parallel epilogue. Buffer overflow (P ~ 1e-160) poisons the
// image's counters -> nms exact fallback, so correctness is unconditional.
__device__ __forceinline__ void proc_f4(u64* skey, u32* scls, int* scnt_sh,
                                        int lane20, float4 v, u32 a){
    int c0 = lane20*4;
    u64 alo = (u64)(0xFFFFFFFFu - a);
    if (v.x > THR0 && c0 != 0){
        int p = atomicAdd(scnt_sh, 1);
        if (p < SBUFC){ skey[p] = ((u64)fmono(v.x) << 32) | alo; scls[p] = c0-1; }
    }
    if (v.y > THR0){
        int p = atomicAdd(scnt_sh, 1);
        if (p < SBUFC){ skey[p] = ((u64)fmono(v.y) << 32) | alo; scls[p] = c0; }
    }
    if (v.z > THR0){
        int p = atomicAdd(scnt_sh, 1);
        if (p < SBUFC){ skey[p] = ((u64)fmono(v.z) << 32) | alo; scls[p] = c0+1; }
    }
    if (v.w > THR0){
        int p = atomicAdd(scnt_sh, 1);
        if (p < SBUFC){ skey[p] = ((u64)fmono(v.w) << 32) | alo; scls[p] = c0+2; }
    }
}

__global__ __launch_bounds__(512) void collect_kernel(const float* __restrict__ y){
    __shared__ u64 skey[SBUFC];
    __shared__ u32 scls[SBUFC];
    __shared__ int scnt_sh;
    int tid = threadIdx.x;
    int b = blockIdx.y, s = blockIdx.x;
    int sh = s & (NSH - 1);
    int a0 = s*APB;
    const float4* base = reinterpret_cast<const float4*>(y) + ((size_t)b*NA + a0)*20;

    if (tid == 0) scnt_sh = 0;
    __syncthreads();

    if (s < NFULL){
        // ---- 5 straight-line unconditional loads
        float4 v0 = base[tid       ];
        float4 v1 = base[tid +  512];
        float4 v2 = base[tid + 1024];
        float4 v3 = base[tid + 1536];
        float4 v4 = base[tid + 2048];
        // lane20 of (tid + q*512): +12 per step mod 20
        int l0 = tid % 20;
        int l1 = l0 + 12; if (l1 >= 20) l1 -= 20;
        int l2 = l0 +  4; if (l2 >= 20) l2 -= 20;
        int l3 = l0 + 16; if (l3 >= 20) l3 -= 20;
        int l4 = l0 +  8; if (l4 >= 20) l4 -= 20;
        proc_f4(skey, scls, &scnt_sh, l0, v0, (u32)(a0 + (tid       )/20));
        proc_f4(skey, scls, &scnt_sh, l1, v1, (u32)(a0 + (tid +  512)/20));
        proc_f4(skey, scls, &scnt_sh, l2, v2, (u32)(a0 + (tid + 1024)/20));
        proc_f4(skey, scls, &scnt_sh, l3, v3, (u32)(a0 + (tid + 1536)/20));
        proc_f4(skey, scls, &scnt_sh, l4, v4, (u32)(a0 + (tid + 2048)/20));
    } else {
        // tail: 32 anchors = 640 f4
        int nf4 = (NA - a0)*20;
        for (int j = tid; j < nf4; j += 512){
            float4 v = base[j];
            proc_f4(skey, scls, &scnt_sh, j % 20, v, (u32)(a0 + j/20));
        }
    }
    __syncthreads();

    int m = scnt_sh;
    if (m > SBUFC){
        // poison: force exact fallback for every class of this image
        if (tid < NCLS) atomicAdd(&g_cnt[(b*NCLS + tid)*NSH], 1 << 20);
        m = SBUFC;
    }
    // ---- epilogue: parallel global emission (one round)
    if (tid < m){
        int t = b*NCLS + (int)scls[tid];
        int pos = atomicAdd(&g_cnt[t*NSH + sh], 1);
        if (pos < SCAP) g_cand[((size_t)t*NSH + sh)*SCAP + pos] = skey[tid];
    }
}

// ---------------------------------------------------------------- classic smem bitonic (desc)
__device__ void bitonic_sort_desc(u64* d, int n){
    int tid = threadIdx.x, nt = blockDim.x;
    for (int k = 2; k <= n; k <<= 1)
        for (int j = k >> 1; j > 0; j >>= 1){
            for (int i = tid; i < n; i += nt){
                int ixj = i ^ j;
                if (ixj > i){
                    u64 a = d[i], b = d[ixj];
                    bool descRegion = ((i & k) == 0);
                    if (descRegion ? (a < b) : (a > b)){ d[i] = b; d[ixj] = a; }
                }
            }
            __syncthreads();
        }
}

__device__ __forceinline__ u64 shfl_xor_u64(u64 x, int m){
    u32 lo = (u32)x, hi = (u32)(x >> 32);
    lo = __shfl_xor_sync(0xFFFFFFFFu, lo, m);
    hi = __shfl_xor_sync(0xFFFFFFFFu, hi, m);
    return ((u64)hi << 32) | lo;
}

// ---------------------------------------------------------------- 1-elem/thread bitonic, n=1024, 1024 threads (desc)
__device__ void sort1024_desc_1t(u64* sm, u64 e){
    int tid = threadIdx.x;
    #pragma unroll
    for (int k = 2; k <= 1024; k <<= 1){
        bool desc = ((tid & k) == 0);
        for (int j = k >> 1; j >= 32; j >>= 1){
            sm[tid] = e;
            __syncthreads();
            u64 o = sm[tid ^ j];
            bool lower = ((tid & j) == 0);
            bool keepmax = (desc == lower);
            e = (keepmax == (e > o)) ? e : o;
            __syncthreads();
        }
        #pragma unroll
        for (int j = 16; j >= 1; j >>= 1){
            if (j <= (k >> 1)){
                u64 o = shfl_xor_u64(e, j);
                bool lower = ((tid & j) == 0);
                bool keepmax = (desc == lower);
                e = (keepmax == (e > o)) ? e : o;
            }
        }
    }
    sm[tid] = e;
    __syncthreads();
}

// ---------------------------------------------------------------- 2-elem/thread hybrid bitonic (final_kernel, 512 thr)
__device__ void hybrid_sort_1024(u64* sm, u64 e0, u64 e1){
    int t = threadIdx.x;
    #pragma unroll
    for (int k = 2; k <= 1024; k <<= 1){
        bool desc = (((2*t) & k) == 0);
        for (int j = k >> 1; j >= 64; j >>= 1){
            sm[2*t] = e0; sm[2*t+1] = e1;
            __syncthreads();
            u64 o0 = sm[(2*t) ^ j], o1 = sm[(2*t+1) ^ j];
            bool lower = ((t & (j >> 1)) == 0);
            bool keepmax = (desc == lower);
            e0 = (keepmax == (e0 > o0)) ? e0 : o0;
            e1 = (keepmax == (e1 > o1)) ? e1 : o1;
            __syncthreads();
        }
        #pragma unroll
        for (int j = 32; j >= 2; j >>= 1){
            if (j <= (k >> 1)){
                int lm = j >> 1;
                u64 o0 = shfl_xor_u64(e0, lm);
                u64 o1 = shfl_xor_u64(e1, lm);
                bool lower = ((t & lm) == 0);
                bool keepmax = (desc == lower);
                e0 = (keepmax == (e0 > o0)) ? e0 : o0;
                e1 = (keepmax == (e1 > o1)) ? e1 : o1;
            }
        }
        {
            u64 a = e0, b = e1;
            u64 mx = a > b ? a : b, mn = a > b ? b : a;
            e0 = desc ? mx : mn;
            e1 = desc ? mn : mx;
        }
    }
    sm[2*t] = e0; sm[2*t+1] = e1;
    __syncthreads();
}

// ---------------------------------------------------------------- cutoff helper (fallback, 1024 threads)
__device__ void find_cutoff_4096_1k(int* hist, int* part, int K, int* c_out){
    int tid = threadIdx.x;
    int p = 0;
    #pragma unroll
    for (int k = 0; k < 4; k++) p += hist[tid*4 + k];
    part[tid] = p;
    __syncthreads();
    for (int off = 1; off < 1024; off <<= 1){
        int v = part[tid];
        if (tid + off < 1024) v += part[tid + off];
        __syncthreads();
        part[tid] = v;
        __syncthreads();
    }
    if (tid == 0 && part[0] < K) *c_out = 0;
    if (part[tid] >= K && (tid == 1023 || part[tid+1] < K)){
        int cum = (tid == 1023) ? 0 : part[tid+1];
        for (int bn = tid*4 + 3; bn >= tid*4; bn--){
            cum += hist[bn];
            if (cum >= K){ *c_out = bn; break; }
        }
    }
    __syncthreads();
}

// ================================================================ nms: fused sort + prefix-mask + fixed point + compact
__global__ __launch_bounds__(1024, 2) void nms_kernel(const float* __restrict__ y,
                                                      const float* __restrict__ bbox,
                                                      const float* __restrict__ anch){
    __shared__ __align__(16) unsigned char arena[32768];  // sbuf(8K)/hist(20K) -> masks(32K)
    __shared__ float4 sboxes[512];
    __shared__ float  sarea[512];
    __shared__ float  svals[512];
    __shared__ int    saidx[512];
    __shared__ u32 keptw[16], validw[16];
    __shared__ int wpref[16];
    __shared__ int sp[NSH+1];
    __shared__ int sovf, scnt, sc1;

    int tid = threadIdx.x;
    int t = blockIdx.x;
    int b = t / NCLS, clsr = t % NCLS;
    int wid = tid >> 5, lane = tid & 31;
    const float4* bbox4 = reinterpret_cast<const float4*>(bbox);
    const float4* anch4 = reinterpret_cast<const float4*>(anch);

    // ---- read + zero sharded counters
    if (tid < NSH){ int c = g_cnt[t*NSH + tid]; g_cnt[t*NSH + tid] = 0; sp[tid+1] = c; }
    __syncthreads();
    if (tid == 0){
        int ov = 0; sp[0] = 0;
        #pragma unroll
        for (int s2 = 0; s2 < NSH; s2++){
            int c = sp[s2+1];
            if (c > SCAP){ ov = 1; c = SCAP; }
            sp[s2+1] = sp[s2] + c;
        }
        sovf = ov;
    }
    __syncthreads();
    int n = sp[NSH];
    bool ovf = (sovf != 0);
    int p1 = sp[1], p2 = sp[2], p3 = sp[3];
    u64* sbuf = (u64*)arena;

    if (!ovf && n >= KPERF && n <= 1024){
        u64 e = 0ull;
        if (tid < n){
            int s2 = (tid >= p1) + (tid >= p2) + (tid >= p3);
            e = g_cand[((size_t)t*NSH + s2)*SCAP + (tid - sp[s2])];
        }
        sort1024_desc_1t(sbuf, e);
    } else if (!ovf && n > 1024 && n <= CAP){
        for (int i = tid; i < CAP; i += 1024){
            u64 v = 0ull;
            if (i < n){
                int s2 = (i >= p1) + (i >= p2) + (i >= p3);
                v = g_cand[((size_t)t*NSH + s2)*SCAP + (i - sp[s2])];
            }
            sbuf[i] = v;
        }
        __syncthreads();
        bitonic_sort_desc(sbuf, CAP);
    } else {
        // ---- exact fallback: histogram-select from the raw column
        int c = clsr + 1;
        const float* col = y + (size_t)b*NA*NC + c;
        int* hist = (int*)arena;                 // 4096 ints
        int* part = (int*)(arena + 16384);       // 1024 ints
        for (int i = tid; i < 4096; i += 1024) hist[i] = 0;
        __syncthreads();
        for (int a = tid; a < NA; a += 1024){
            float v = col[(size_t)a*NC];
            if (v > SCORE_THR){
                int bn = (int)(v*4096.f); bn = bn > 4095 ? 4095 : bn;
                atomicAdd(&hist[bn], 1);
            }
        }
        __syncthreads();
        find_cutoff_4096_1k(hist, part, KPERF, &sc1);
        int c1 = sc1;
        if (tid == 0) scnt = 0;
        __syncthreads();
        for (int a = tid; a < NA; a += 1024){
            float v = col[(size_t)a*NC];
            if (v > SCORE_THR){
                int bn = (int)(v*4096.f); bn = bn > 4095 ? 4095 : bn;
                if (bn >= c1){
                    int pos = atomicAdd(&scnt, 1);
                    if (pos < CAP)
                        sbuf[pos] = ((u64)fmono(v) << 32) | (u64)(0xFFFFFFFFu - (u32)a);
                }
            }
        }
        __syncthreads();
        int m = min(scnt, CAP);
        int n2 = 1024;
        while (n2 < m) n2 <<= 1;
        for (int i = m + tid; i < n2; i += 1024) sbuf[i] = 0ull;
        __syncthreads();
        bitonic_sort_desc(sbuf, n2);
    }

    // ---- extract top-500 + decode into smem
    bool valid = false;
    if (tid < 512){
        float v = -1.0f; int a = 0;
        float4 bx = make_float4(0.f, 0.f, 0.f, 0.f);
        if (tid < KPERF){
            u64 key = sbuf[tid];
            u32 mk = (u32)(key >> 32);
            if (mk > 0x80000000u){
                v = fmono_inv(mk);
                a = (int)(0xFFFFFFFFu - (u32)key);
                bx = decode_box(bbox4[(size_t)b*NA + a], anch4[a]);
            }
        }
        svals[tid] = v; saidx[tid] = a;
        sboxes[tid] = bx;
        sarea[tid] = (bx.z - bx.x)*(bx.w - bx.y);
        valid = (v > 0.0f);
    }
    {
        u32 bal = __ballot_sync(0xFFFFFFFFu, valid);
        if (lane == 0 && wid < 16) validw[wid] = bal;
    }
    __syncthreads();    // sbuf dead; arena reused as masks

    u32* masks = (u32*)arena;   // masks[r*16 + w], lower triangle only

    // ============ phase A: prefix rows [0, RPRE) ============
    #pragma unroll 1
    for (int w = 0; w < RPRE/32; w++){
        int j = w*32 + lane;
        float4 bj = sboxes[j];
        float areaj = sarea[j];
        for (int r = 32*w + wid; r < RPRE; r += 32){
            float4 bi = sboxes[r];
            float areai = sarea[r];
            bool o = false;
            if (j < r){
                float lx = fmaxf(bi.x, bj.x), ly = fmaxf(bi.y, bj.y);
                float rx = fminf(bi.z, bj.z), ry = fminf(bi.w, bj.w);
                float iw = fmaxf(rx - lx, 0.f), ih = fmaxf(ry - ly, 0.f);
                float inter = iw*ih;
                float uni = areai + areaj - inter;
                o = inter > 0.5f*fmaxf(uni, 1e-9f);
            }
            u32 bits = __ballot_sync(0xFFFFFFFFu, o);
            if (lane == 0) masks[r*16 + w] = bits;
        }
    }
    if (tid < 16) keptw[tid] = validw[tid];
    __syncthreads();

    // ---- fixed point over prefix
    bool vld = (tid < KPERF) ? (svals[tid] > 0.0f) : false;
    bool converged = false;
    for (int it = 0; it < 16; it++){
        bool supp = false;
        if (tid < RPRE){
            int w0 = tid >> 5;
            const u32* row = masks + tid*16;
            for (int w = 0; w <= w0; w++) supp |= (keptw[w] & row[w]) != 0u;
        }
        bool nk = vld && !supp && (tid < RPRE);
        u32 nb = __ballot_sync(0xFFFFFFFFu, nk);
        int ch = 0;
        if (lane == 0 && wid < RPRE/32 && nb != keptw[wid]){ keptw[wid] = nb; ch = 1; }
        if (__syncthreads_or(ch) == 0){ converged = true; break; }
    }
    if (!converged){
        if (tid < 32){
            u32 kw = 0;
            for (int i = 0; i < RPRE; i++){
                u32 m = (tid <= (i >> 5)) ? masks[i*16 + tid] : 0u;
                bool supp = __any_sync(0xFFFFFFFFu, (m & kw) != 0u);
                bool vi = svals[i] > 0.0f;
                if (vi && !supp && tid == (i >> 5)) kw |= 1u << (i & 31);
            }
            if (tid < RPRE/32) keptw[tid] = kw;
        }
        __syncthreads();
    }

    // ---- exactness check
    int kc, vcnt;
    {
        if (tid == 0){
            int a = 0, v2 = 0;
            #pragma unroll
            for (int w = 0; w < RPRE/32; w++) a += __popc(keptw[w]);
            #pragma unroll
            for (int w = 0; w < 16; w++) v2 += __popc(validw[w]);
            sp[0] = a; sp[1] = v2;
        }
        __syncthreads();
        kc = sp[0]; vcnt = sp[1];
    }

    if (!(kc >= KEEPC || vcnt <= RPRE)){
        // ============ phase B (rare): full 500 rows ============
        __syncthreads();
        #pragma unroll 1
        for (int w = 0; w < 16; w++){
            int j = w*32 + lane;
            float4 bj = sboxes[j];
            float areaj = sarea[j];
            for (int r = 32*w + wid; r < KPERF; r += 32){
                float4 bi = sboxes[r];
                float areai = sarea[r];
                bool o = false;
                if (j < r){
                    float lx = fmaxf(bi.x, bj.x), ly = fmaxf(bi.y, bj.y);
                    float rx = fminf(bi.z, bj.z), ry = fminf(bi.w, bj.w);
                    float iw = fmaxf(rx - lx, 0.f), ih = fmaxf(ry - ly, 0.f);
                    float inter = iw*ih;
                    float uni = areai + areaj - inter;
                    o = inter > 0.5f*fmaxf(uni, 1e-9f);
                }
                u32 bits = __ballot_sync(0xFFFFFFFFu, o);
                if (lane == 0) masks[r*16 + w] = bits;
            }
        }
        if (tid < 16) keptw[tid] = validw[tid];
        __syncthreads();

        converged = false;
        for (int it = 0; it < 16; it++){
            bool supp = false;
            if (tid < KPERF){
                int w0 = tid >> 5;
                const u32* row = masks + tid*16;
                for (int w = 0; w <= w0; w++) supp |= (keptw[w] & row[w]) != 0u;
            }
            bool nk = vld && !supp;
            u32 nb = __ballot_sync(0xFFFFFFFFu, nk);
            int ch = 0;
            if (lane == 0 && wid < 16 && nb != keptw[wid]){ keptw[wid] = nb; ch = 1; }
            if (__syncthreads_or(ch) == 0){ converged = true; break; }
        }
        if (!converged){
            if (tid < 32){
                u32 kw = 0;
                for (int i = 0; i < KPERF; i++){
                    u32 m = (tid <= (i >> 5)) ? masks[i*16 + tid] : 0u;
                    bool supp = __any_sync(0xFFFFFFFFu, (m & kw) != 0u);
                    bool vi = svals[i] > 0.0f;
                    if (vi && !supp && tid == (i >> 5)) kw |= 1u << (i & 31);
                }
                if (tid < 16) keptw[tid] = kw;
            }
            __syncthreads();
        }
        if (tid == 0){
            int a = 0;
            #pragma unroll
            for (int w = 0; w < 16; w++) a += __popc(keptw[w]);
            sp[0] = a;
        }
        __syncthreads();
        kc = sp[0];
    }
    // stale keptw[8..15] on phase-A exit are safe (kc>=KEEPC drops ranks>=KEEPC,
    // or vcnt<=RPRE makes them zero).

    if (tid == 0){
        int acc = 0;
        #pragma unroll
        for (int w = 0; w < 16; w++){ wpref[w] = acc; acc += __popc(keptw[w]); }
    }
    __syncthreads();

    if (tid < KPERF){
        int w = tid >> 5, b2 = tid & 31;
        if ((keptw[w] >> b2) & 1u){
            int rank = wpref[w] + __popc(keptw[w] & ((1u << b2) - 1u));
            if (rank < KEEPC){
                g_fval [t*KEEPC + rank] = svals[tid];
                g_fflat[t*KEEPC + rank] = clsr*KPERF + tid;
                g_faidx[t*KEEPC + rank] = saidx[tid];
            }
        }
    }
    if (tid < KEEPC && tid >= kc) g_fval[t*KEEPC + tid] = -1.0f;
}

// ---------------------------------------------------------------- final binning helpers
__device__ __forceinline__ int bin1(float v){
    float t = (v - 0.99f)*409600.0f;
    int b = (int)t;
    return b < 0 ? 0 : (b > 4095 ? 4095 : b);
}
__device__ __forceinline__ int bin2(float v, int c1){
    if (c1 > 0){
        float t = (v - 0.99f)*409600.0f - (float)c1;
        int s = (int)(t*4096.0f);
        return s < 0 ? 0 : (s > 4095 ? 4095 : s);
    } else {
        int s = (int)(v*4096.0f);
        return s < 0 ? 0 : (s > 4095 ? 4095 : s);
    }
}

// ================================================================ final: per-image global top-100 + gather
__global__ __launch_bounds__(512) void final_kernel(const float* __restrict__ y_pred,
                                                    const float* __restrict__ bbox,
                                                    const float* __restrict__ anch,
                                                    float* __restrict__ out){
    __shared__ int hist[4096];
    __shared__ int wt[16];
    __shared__ int sc, sab, sbin, sc2, scnt;
    __shared__ u64 skey[1024];
    __shared__ int sA[KPROP];
    int tid = threadIdx.x;
    int lane = tid & 31, wrp = tid >> 5;
    int b = blockIdx.x;
    const int gbase = b*MFIN;
    const float4* bbox4 = reinterpret_cast<const float4*>(bbox);
    const float4* anch4 = reinterpret_cast<const float4*>(anch);

    float vreg[RPT];
    #pragma unroll
    for (int k = 0; k < RPT; k++){
        int idx = tid + k*512;
        vreg[k] = (idx < MFIN) ? g_fval[gbase + idx] : -1.0f;
    }

    for (int i = tid; i < 4096; i += 512) hist[i] = 0;
    __syncthreads();
    #pragma unroll
    for (int k = 0; k < RPT; k++){
        float v = vreg[k];
        if (v > 0.f) atomicAdd(&hist[bin1(v)], 1);
    }
    __syncthreads();

    {
        int p = 0;
        #pragma unroll
        for (int k = 0; k < 8; k++) p += hist[tid*8 + k];
        int s = p;
        #pragma unroll
        for (int off = 1; off < 32; off <<= 1){
            int v = __shfl_down_sync(0xFFFFFFFFu, s, off);
            if (lane + off < 32) s += v;
        }
        if (lane == 0) wt[wrp] = s;
        __syncthreads();
        int wsuf = 0;
        #pragma unroll
        for (int j = 0; j < 16; j++) if (j > wrp) wsuf += wt[j];
        int St = s + wsuf;
        if (tid == 0 && St < KPROP){ sc = 0; sab = 0; sbin = 0; }
        if (St >= KPROP && St - p < KPROP){
            int cum = St - p;
            for (int bn = tid*8 + 7; bn >= tid*8; bn--){
                cum += hist[bn];
                if (cum >= KPROP){ sc = bn; sab = cum - hist[bn]; sbin = hist[bn]; break; }
            }
        }
        __syncthreads();
    }
    int c1 = sc, ab1 = sab;
    int c2 = 0;
    bool need2 = (ab1 + sbin > 512);

    if (need2){
        for (int i = tid; i < 4096; i += 512) hist[i] = 0;
        __syncthreads();
        #pragma unroll
        for (int k = 0; k < RPT; k++){
            float v = vreg[k];
            if (v > 0.f && bin1(v) == c1) atomicAdd(&hist[bin2(v, c1)], 1);
        }
        __syncthreads();
        int K2 = KPROP - ab1;
        int p = 0;
        #pragma unroll
        for (int k = 0; k < 8; k++) p += hist[tid*8 + k];
        int s = p;
        #pragma unroll
        for (int off = 1; off < 32; off <<= 1){
            int v = __shfl_down_sync(0xFFFFFFFFu, s, off);
            if (lane + off < 32) s += v;
        }
        if (lane == 0) wt[wrp] = s;
        __syncthreads();
        int wsuf = 0;
        #pragma unroll
        for (int j = 0; j < 16; j++) if (j > wrp) wsuf += wt[j];
        int St = s + wsuf;
        if (tid == 0 && St < K2) sc2 = 0;
        if (St >= K2 && St - p < K2){
            int cum = St - p;
            for (int bn = tid*8 + 7; bn >= tid*8; bn--){
                cum += hist[bn];
                if (cum >= K2){ sc2 = bn; break; }
            }
        }
        __syncthreads();
        c2 = sc2;
    }

    if (tid == 0) scnt = 0;
    __syncthreads();
    #pragma unroll
    for (int k = 0; k < RPT; k++){
        float v = vreg[k];
        if (v > 0.f){
            int bn = bin1(v);
            bool sel = bn > c1;
            if (bn == c1) sel = !need2 || (bin2(v, c1) >= c2);
            if (sel){
                int i = tid + k*512;
                int pos = atomicAdd(&scnt, 1);
                if (pos < 512){
                    u32 fflat = (u32)g_fflat[gbase + i];
                    skey[pos] = ((u64)fmono(v) << 32) | ((u64)(65535u - fflat) << 14) | (u64)i;
                }
            }
        }
    }
    __syncthreads();
    int n = min(scnt, 512);
    for (int i = n + tid; i < 1024; i += 512) skey[i] = 0ull;
    __syncthreads();

    {
        u64 e0 = skey[2*tid], e1 = skey[2*tid + 1];
        hybrid_sort_1024(skey, e0, e1);
    }

    if (tid < KPROP){
        u64 key = skey[tid];
        u32 mk = (u32)(key >> 32);
        if (mk > 0x80000000u){
            int slot = (int)(key & 0x3FFFull);
            sA[tid] = g_faidx[gbase + slot];
        } else sA[tid] = -1;
    }
    __syncthreads();

    float* oscores = out;                         // [B,PROP,C]
    float* oboxes  = out + NB*KPROP*NC;           // [B,PROP,4]
    #pragma unroll
    for (int k = 0; k < 16; k++){
        int idx = tid + k*512;
        if (idx < KPROP*NC){
            int p = idx / NC, cc = idx % NC;
            int a = sA[p];
            oscores[(b*KPROP + p)*NC + cc] = (a >= 0) ? y_pred[((size_t)b*NA + a)*NC + cc] : 0.f;
        }
    }
    if (tid < KPROP){
        int a = sA[tid];
        float4 bx = make_float4(0.f, 0.f, 0.f, 0.f);
        if (a >= 0) bx = decode_box(bbox4[(size_t)b*NA + a], anch4[a]);
        reinterpret_cast<float4*>(oboxes)[b*KPROP + tid] = bx;
    }
}

// ----------------------------------------------------------------
extern "C" void kernel_launch(void* const* d_in, const int* in_sizes, int n_in,
                              void* d_out, int out_size){
    (void)in_sizes; (void)n_in; (void)out_size;
    const float* y    = (const float*)d_in[0];   // [B,A,C]
    const float* bbox = (const float*)d_in[1];   // [B,A,4]
    const float* anch = (const float*)d_in[2];   // [A,4]
    float* out = (float*)d_out;

    collect_kernel<<<dim3(NBLK, NB), 512>>>(y);      // 1
    nms_kernel<<<NTASK, 1024>>>(y, bbox, anch);      // 2
    final_kernel<<<NB, 512>>>(y, bbox, anch, out);   // 3
    // profiled slot 4 = collect_kernel of iteration 2
}

// round 17
// speedup vs baseline: 1.1066x; 1.1066x over previous
#include <cuda_runtime.h>

#define NB 2
#define NA 100000
#define NC 80
#define NCLS 79          // classes excluding background (class 0)
#define KPERF 500
#define KPROP 100
#define NTASK (NB*NCLS)  // 158
#define SCORE_THR 0.05f
#define THR0 0.992f      // static candidate threshold (self-checked; fallback if violated)
#define NSH 4            // counter shards
#define SCAP 512         // per-shard capacity
#define CAP 2048
#define APB 32           // anchors per collect block (32*20 = 640 f4 = 128 thr * 5)
#define NFULL (NA/APB)   // 3125 exactly; no tail
#define SBUFC 128        // per-block smem candidate buffer (expected ~20, +24 sigma)
#define RPRE 192         // NMS prefix rows (exactness certified at runtime)
#define KEEPC 128        // kept entries per class forwarded to final
#define MFIN (NCLS*KEEPC)   // 10112
#define RPT 20           // ceil(MFIN/512)

typedef unsigned long long u64;
typedef unsigned int u32;

// ---- scratch (static device arrays; allocation-free) ----
__device__ int    g_cnt[NTASK*NSH];
__device__ u64    g_cand[(size_t)NTASK*NSH*SCAP];   // 2.6 MB
__device__ float  g_fval[NTASK*KEEPC];
__device__ int    g_fflat[NTASK*KEEPC];
__device__ int    g_faidx[NTASK*KEEPC];

__device__ __forceinline__ u32 fmono(float f){
    u32 u = __float_as_uint(f);
    return (u & 0x80000000u) ? ~u : (u | 0x80000000u);
}
__device__ __forceinline__ float fmono_inv(u32 k){
    return __uint_as_float((k & 0x80000000u) ? (k & 0x7FFFFFFFu) : ~k);
}

// mmdet delta decode + clip to [0,1]
__device__ __forceinline__ float4 decode_box(float4 d, float4 an){
    const float MAXR = 4.135166556742356f;   // |ln(16/1000)|
    float dw = fminf(fmaxf(d.z, -MAXR), MAXR);
    float dh = fminf(fmaxf(d.w, -MAXR), MAXR);
    float pw = an.z - an.x, ph = an.w - an.y;
    float px = (an.x + an.z)*0.5f, py = (an.y + an.w)*0.5f;
    float gw = pw*expf(dw), gh = ph*expf(dh);
    float gx = px + pw*d.x, gy = py + ph*d.y;
    float4 o;
    o.x = fminf(fmaxf(gx - gw*0.5f, 0.f), 1.f);
    o.y = fminf(fmaxf(gy - gh*0.5f, 0.f), 1.f);
    o.z = fminf(fmaxf(gx + gw*0.5f, 0.f), 1.f);
    o.w = fminf(fmaxf(gy + gh*0.5f, 0.f), 1.f);
    return o;
}

// ================================================================ collect: smem-batched candidates > THR0
// 128 threads x 5 straight-line loads = one 32-anchor chunk; no tail block.
__device__ __forceinline__ void proc_f4(u64* skey, u32* scls, int* scnt_sh,
                                        int lane20, float4 v, u32 a){
    int c0 = lane20*4;
    u64 alo = (u64)(0xFFFFFFFFu - a);
    if (v.x > THR0 && c0 != 0){
        int p = atomicAdd(scnt_sh, 1);
        if (p < SBUFC){ skey[p] = ((u64)fmono(v.x) << 32) | alo; scls[p] = c0-1; }
    }
    if (v.y > THR0){
        int p = atomicAdd(scnt_sh, 1);
        if (p < SBUFC){ skey[p] = ((u64)fmono(v.y) << 32) | alo; scls[p] = c0; }
    }
    if (v.z > THR0){
        int p = atomicAdd(scnt_sh, 1);
        if (p < SBUFC){ skey[p] = ((u64)fmono(v.z) << 32) | alo; scls[p] = c0+1; }
    }
    if (v.w > THR0){
        int p = atomicAdd(scnt_sh, 1);
        if (p < SBUFC){ skey[p] = ((u64)fmono(v.w) << 32) | alo; scls[p] = c0+2; }
    }
}

__global__ __launch_bounds__(128, 12) void collect_kernel(const float* __restrict__ y){
    __shared__ u64 skey[SBUFC];
    __shared__ u32 scls[SBUFC];
    __shared__ int scnt_sh;
    int tid = threadIdx.x;
    int b = blockIdx.y, s = blockIdx.x;
    int sh = s & (NSH - 1);
    int a0 = s*APB;
    const float4* base = reinterpret_cast<const float4*>(y) + ((size_t)b*NA + a0)*20;

    if (tid == 0) scnt_sh = 0;
    __syncthreads();

    // ---- 5 straight-line unconditional loads (640 f4 total)
    float4 v0 = base[tid      ];
    float4 v1 = base[tid + 128];
    float4 v2 = base[tid + 256];
    float4 v3 = base[tid + 384];
    float4 v4 = base[tid + 512];
    // lane20 of (tid + q*128): +8 per step mod 20
    int l0 = tid % 20;
    int l1 = l0 +  8; if (l1 >= 20) l1 -= 20;
    int l2 = l0 + 16; if (l2 >= 20) l2 -= 20;
    int l3 = l0 +  4; if (l3 >= 20) l3 -= 20;
    int l4 = l0 + 12; if (l4 >= 20) l4 -= 20;
    proc_f4(skey, scls, &scnt_sh, l0, v0, (u32)(a0 + (tid      )/20));
    proc_f4(skey, scls, &scnt_sh, l1, v1, (u32)(a0 + (tid + 128)/20));
    proc_f4(skey, scls, &scnt_sh, l2, v2, (u32)(a0 + (tid + 256)/20));
    proc_f4(skey, scls, &scnt_sh, l3, v3, (u32)(a0 + (tid + 384)/20));
    proc_f4(skey, scls, &scnt_sh, l4, v4, (u32)(a0 + (tid + 512)/20));
    __syncthreads();

    int m = scnt_sh;
    if (m > SBUFC){
        // poison: force exact fallback for every class of this image
        if (tid < NCLS) atomicAdd(&g_cnt[(b*NCLS + tid)*NSH], 1 << 20);
        m = SBUFC;
    }
    // ---- epilogue: parallel global emission (one round)
    if (tid < m){
        int t = b*NCLS + (int)scls[tid];
        int pos = atomicAdd(&g_cnt[t*NSH + sh], 1);
        if (pos < SCAP) g_cand[((size_t)t*NSH + sh)*SCAP + pos] = skey[tid];
    }
}

// ---------------------------------------------------------------- classic smem bitonic (desc)
__device__ void bitonic_sort_desc(u64* d, int n){
    int tid = threadIdx.x, nt = blockDim.x;
    for (int k = 2; k <= n; k <<= 1)
        for (int j = k >> 1; j > 0; j >>= 1){
            for (int i = tid; i < n; i += nt){
                int ixj = i ^ j;
                if (ixj > i){
                    u64 a = d[i], b = d[ixj];
                    bool descRegion = ((i & k) == 0);
                    if (descRegion ? (a < b) : (a > b)){ d[i] = b; d[ixj] = a; }
                }
            }
            __syncthreads();
        }
}

__device__ __forceinline__ u64 shfl_xor_u64(u64 x, int m){
    u32 lo = (u32)x, hi = (u32)(x >> 32);
    lo = __shfl_xor_sync(0xFFFFFFFFu, lo, m);
    hi = __shfl_xor_sync(0xFFFFFFFFu, hi, m);
    return ((u64)hi << 32) | lo;
}

// ---------------------------------------------------------------- 1-elem/thread bitonic, n=1024, 1024 threads (desc)
__device__ void sort1024_desc_1t(u64* sm, u64 e){
    int tid = threadIdx.x;
    #pragma unroll
    for (int k = 2; k <= 1024; k <<= 1){
        bool desc = ((tid & k) == 0);
        for (int j = k >> 1; j >= 32; j >>= 1){
            sm[tid] = e;
            __syncthreads();
            u64 o = sm[tid ^ j];
            bool lower = ((tid & j) == 0);
            bool keepmax = (desc == lower);
            e = (keepmax == (e > o)) ? e : o;
            __syncthreads();
        }
        #pragma unroll
        for (int j = 16; j >= 1; j >>= 1){
            if (j <= (k >> 1)){
                u64 o = shfl_xor_u64(e, j);
                bool lower = ((tid & j) == 0);
                bool keepmax = (desc == lower);
                e = (keepmax == (e > o)) ? e : o;
            }
        }
    }
    sm[tid] = e;
    __syncthreads();
}

// ---------------------------------------------------------------- 2-elem/thread hybrid bitonic (final_kernel, 512 thr)
__device__ void hybrid_sort_1024(u64* sm, u64 e0, u64 e1){
    int t = threadIdx.x;
    #pragma unroll
    for (int k = 2; k <= 1024; k <<= 1){
        bool desc = (((2*t) & k) == 0);
        for (int j = k >> 1; j >= 64; j >>= 1){
            sm[2*t] = e0; sm[2*t+1] = e1;
            __syncthreads();
            u64 o0 = sm[(2*t) ^ j], o1 = sm[(2*t+1) ^ j];
            bool lower = ((t & (j >> 1)) == 0);
            bool keepmax = (desc == lower);
            e0 = (keepmax == (e0 > o0)) ? e0 : o0;
            e1 = (keepmax == (e1 > o1)) ? e1 : o1;
            __syncthreads();
        }
        #pragma unroll
        for (int j = 32; j >= 2; j >>= 1){
            if (j <= (k >> 1)){
                int lm = j >> 1;
                u64 o0 = shfl_xor_u64(e0, lm);
                u64 o1 = shfl_xor_u64(e1, lm);
                bool lower = ((t & lm) == 0);
                bool keepmax = (desc == lower);
                e0 = (keepmax == (e0 > o0)) ? e0 : o0;
                e1 = (keepmax == (e1 > o1)) ? e1 : o1;
            }
        }
        {
            u64 a = e0, b = e1;
            u64 mx = a > b ? a : b, mn = a > b ? b : a;
            e0 = desc ? mx : mn;
            e1 = desc ? mn : mx;
        }
    }
    sm[2*t] = e0; sm[2*t+1] = e1;
    __syncthreads();
}

// ---------------------------------------------------------------- cutoff helper (fallback, 1024 threads)
__device__ void find_cutoff_4096_1k(int* hist, int* part, int K, int* c_out){
    int tid = threadIdx.x;
    int p = 0;
    #pragma unroll
    for (int k = 0; k < 4; k++) p += hist[tid*4 + k];
    part[tid] = p;
    __syncthreads();
    for (int off = 1; off < 1024; off <<= 1){
        int v = part[tid];
        if (tid + off < 1024) v += part[tid + off];
        __syncthreads();
        part[tid] = v;
        __syncthreads();
    }
    if (tid == 0 && part[0] < K) *c_out = 0;
    if (part[tid] >= K && (tid == 1023 || part[tid+1] < K)){
        int cum = (tid == 1023) ? 0 : part[tid+1];
        for (int bn = tid*4 + 3; bn >= tid*4; bn--){
            cum += hist[bn];
            if (cum >= K){ *c_out = bn; break; }
        }
    }
    __syncthreads();
}

// ================================================================ nms: fused sort + prefix-mask + fixed point + compact
__global__ __launch_bounds__(1024, 2) void nms_kernel(const float* __restrict__ y,
                                                      const float* __restrict__ bbox,
                                                      const float* __restrict__ anch){
    __shared__ __align__(16) unsigned char arena[32768];  // sbuf(8K)/hist(20K) -> masks(32K)
    __shared__ float4 sboxes[512];
    __shared__ float  sarea[512];
    __shared__ float  svals[512];
    __shared__ int    saidx[512];
    __shared__ u32 keptw[16], validw[16];
    __shared__ int wpref[16];
    __shared__ int sp[NSH+1];
    __shared__ int sovf, scnt, sc1;

    int tid = threadIdx.x;
    int t = blockIdx.x;
    int b = t / NCLS, clsr = t % NCLS;
    int wid = tid >> 5, lane = tid & 31;
    const float4* bbox4 = reinterpret_cast<const float4*>(bbox);
    const float4* anch4 = reinterpret_cast<const float4*>(anch);

    // ---- read + zero sharded counters
    if (tid < NSH){ int c = g_cnt[t*NSH + tid]; g_cnt[t*NSH + tid] = 0; sp[tid+1] = c; }
    __syncthreads();
    if (tid == 0){
        int ov = 0; sp[0] = 0;
        #pragma unroll
        for (int s2 = 0; s2 < NSH; s2++){
            int c = sp[s2+1];
            if (c > SCAP){ ov = 1; c = SCAP; }
            sp[s2+1] = sp[s2] + c;
        }
        sovf = ov;
    }
    __syncthreads();
    int n = sp[NSH];
    bool ovf = (sovf != 0);
    int p1 = sp[1], p2 = sp[2], p3 = sp[3];
    u64* sbuf = (u64*)arena;

    if (!ovf && n >= KPERF && n <= 1024){
        u64 e = 0ull;
        if (tid < n){
            int s2 = (tid >= p1) + (tid >= p2) + (tid >= p3);
            e = g_cand[((size_t)t*NSH + s2)*SCAP + (tid - sp[s2])];
        }
        sort1024_desc_1t(sbuf, e);
    } else if (!ovf && n > 1024 && n <= CAP){
        for (int i = tid; i < CAP; i += 1024){
            u64 v = 0ull;
            if (i < n){
                int s2 = (i >= p1) + (i >= p2) + (i >= p3);
                v = g_cand[((size_t)t*NSH + s2)*SCAP + (i - sp[s2])];
            }
            sbuf[i] = v;
        }
        __syncthreads();
        bitonic_sort_desc(sbuf, CAP);
    } else {
        // ---- exact fallback: histogram-select from the raw column
        int c = clsr + 1;
        const float* col = y + (size_t)b*NA*NC + c;
        int* hist = (int*)arena;                 // 4096 ints
        int* part = (int*)(arena + 16384);       // 1024 ints
        for (int i = tid; i < 4096; i += 1024) hist[i] = 0;
        __syncthreads();
        for (int a = tid; a < NA; a += 1024){
            float v = col[(size_t)a*NC];
            if (v > SCORE_THR){
                int bn = (int)(v*4096.f); bn = bn > 4095 ? 4095 : bn;
                atomicAdd(&hist[bn], 1);
            }
        }
        __syncthreads();
        find_cutoff_4096_1k(hist, part, KPERF, &sc1);
        int c1 = sc1;
        if (tid == 0) scnt = 0;
        __syncthreads();
        for (int a = tid; a < NA; a += 1024){
            float v = col[(size_t)a*NC];
            if (v > SCORE_THR){
                int bn = (int)(v*4096.f); bn = bn > 4095 ? 4095 : bn;
                if (bn >= c1){
                    int pos = atomicAdd(&scnt, 1);
                    if (pos < CAP)
                        sbuf[pos] = ((u64)fmono(v) << 32) | (u64)(0xFFFFFFFFu - (u32)a);
                }
            }
        }
        __syncthreads();
        int m = min(scnt, CAP);
        int n2 = 1024;
        while (n2 < m) n2 <<= 1;
        for (int i = m + tid; i < n2; i += 1024) sbuf[i] = 0ull;
        __syncthreads();
        bitonic_sort_desc(sbuf, n2);
    }

    // ---- extract top-500 + decode into smem
    bool valid = false;
    if (tid < 512){
        float v = -1.0f; int a = 0;
        float4 bx = make_float4(0.f, 0.f, 0.f, 0.f);
        if (tid < KPERF){
            u64 key = sbuf[tid];
            u32 mk = (u32)(key >> 32);
            if (mk > 0x80000000u){
                v = fmono_inv(mk);
                a = (int)(0xFFFFFFFFu - (u32)key);
                bx = decode_box(bbox4[(size_t)b*NA + a], anch4[a]);
            }
        }
        svals[tid] = v; saidx[tid] = a;
        sboxes[tid] = bx;
        sarea[tid] = (bx.z - bx.x)*(bx.w - bx.y);
        valid = (v > 0.0f);
    }
    {
        u32 bal = __ballot_sync(0xFFFFFFFFu, valid);
        if (lane == 0 && wid < 16) validw[wid] = bal;
    }
    __syncthreads();    // sbuf dead; arena reused as masks

    u32* masks = (u32*)arena;   // masks[r*16 + w], lower triangle only

    // ============ phase A: prefix rows [0, RPRE) ============
    #pragma unroll 1
    for (int w = 0; w < RPRE/32; w++){
        int j = w*32 + lane;
        float4 bj = sboxes[j];
        float areaj = sarea[j];
        for (int r = 32*w + wid; r < RPRE; r += 32){
            float4 bi = sboxes[r];
            float areai = sarea[r];
            bool o = false;
            if (j < r){
                float lx = fmaxf(bi.x, bj.x), ly = fmaxf(bi.y, bj.y);
                float rx = fminf(bi.z, bj.z), ry = fminf(bi.w, bj.w);
                float iw = fmaxf(rx - lx, 0.f), ih = fmaxf(ry - ly, 0.f);
                float inter = iw*ih;
                float uni = areai + areaj - inter;
                o = inter > 0.5f*fmaxf(uni, 1e-9f);
            }
            u32 bits = __ballot_sync(0xFFFFFFFFu, o);
            if (lane == 0) masks[r*16 + w] = bits;
        }
    }
    if (tid < 16) keptw[tid] = validw[tid];
    __syncthreads();

    // ---- fixed point over prefix
    bool vld = (tid < KPERF) ? (svals[tid] > 0.0f) : false;
    bool converged = false;
    for (int it = 0; it < 16; it++){
        bool supp = false;
        if (tid < RPRE){
            int w0 = tid >> 5;
            const u32* row = masks + tid*16;
            for (int w = 0; w <= w0; w++) supp |= (keptw[w] & row[w]) != 0u;
        }
        bool nk = vld && !supp && (tid < RPRE);
        u32 nb = __ballot_sync(0xFFFFFFFFu, nk);
        int ch = 0;
        if (lane == 0 && wid < RPRE/32 && nb != keptw[wid]){ keptw[wid] = nb; ch = 1; }
        if (__syncthreads_or(ch) == 0){ converged = true; break; }
    }
    if (!converged){
        if (tid < 32){
            u32 kw = 0;
            for (int i = 0; i < RPRE; i++){
                u32 m = (tid <= (i >> 5)) ? masks[i*16 + tid] : 0u;
                bool supp = __any_sync(0xFFFFFFFFu, (m & kw) != 0u);
                bool vi = svals[i] > 0.0f;
                if (vi && !supp && tid == (i >> 5)) kw |= 1u << (i & 31);
            }
            if (tid < RPRE/32) keptw[tid] = kw;
        }
        __syncthreads();
    }

    // ---- exactness check
    int kc, vcnt;
    {
        if (tid == 0){
            int a = 0, v2 = 0;
            #pragma unroll
            for (int w = 0; w < RPRE/32; w++) a += __popc(keptw[w]);
            #pragma unroll
            for (int w = 0; w < 16; w++) v2 += __popc(validw[w]);
            sp[0] = a; sp[1] = v2;
        }
        __syncthreads();
        kc = sp[0]; vcnt = sp[1];
    }

    if (!(kc >= KEEPC || vcnt <= RPRE)){
        // ============ phase B (rare): full 500 rows ============
        __syncthreads();
        #pragma unroll 1
        for (int w = 0; w < 16; w++){
            int j = w*32 + lane;
            float4 bj = sboxes[j];
            float areaj = sarea[j];
            for (int r = 32*w + wid; r < KPERF; r += 32){
                float4 bi = sboxes[r];
                float areai = sarea[r];
                bool o = false;
                if (j < r){
                    float lx = fmaxf(bi.x, bj.x), ly = fmaxf(bi.y, bj.y);
                    float rx = fminf(bi.z, bj.z), ry = fminf(bi.w, bj.w);
                    float iw = fmaxf(rx - lx, 0.f), ih = fmaxf(ry - ly, 0.f);
                    float inter = iw*ih;
                    float uni = areai + areaj - inter;
                    o = inter > 0.5f*fmaxf(uni, 1e-9f);
                }
                u32 bits = __ballot_sync(0xFFFFFFFFu, o);
                if (lane == 0) masks[r*16 + w] = bits;
            }
        }
        if (tid < 16) keptw[tid] = validw[tid];
        __syncthreads();

        converged = false;
        for (int it = 0; it < 16; it++){
            bool supp = false;
            if (tid < KPERF){
                int w0 = tid >> 5;
                const u32* row = masks + tid*16;
                for (int w = 0; w <= w0; w++) supp |= (keptw[w] & row[w]) != 0u;
            }
            bool nk = vld && !supp;
            u32 nb = __ballot_sync(0xFFFFFFFFu, nk);
            int ch = 0;
            if (lane == 0 && wid < 16 && nb != keptw[wid]){ keptw[wid] = nb; ch = 1; }
            if (__syncthreads_or(ch) == 0){ converged = true; break; }
        }
        if (!converged){
            if (tid < 32){
                u32 kw = 0;
                for (int i = 0; i < KPERF; i++){
                    u32 m = (tid <= (i >> 5)) ? masks[i*16 + tid] : 0u;
                    bool supp = __any_sync(0xFFFFFFFFu, (m & kw) != 0u);
                    bool vi = svals[i] > 0.0f;
                    if (vi && !supp && tid == (i >> 5)) kw |= 1u << (i & 31);
                }
                if (tid < 16) keptw[tid] = kw;
            }
            __syncthreads();
        }
        if (tid == 0){
            int a = 0;
            #pragma unroll
            for (int w = 0; w < 16; w++) a += __popc(keptw[w]);
            sp[0] = a;
        }
        __syncthreads();
        kc = sp[0];
    }
    // stale keptw[RPRE/32..15] on phase-A exit are safe (kc>=KEEPC drops
    // ranks>=KEEPC, or vcnt<=RPRE makes them zero).

    if (tid == 0){
        int acc = 0;
        #pragma unroll
        for (int w = 0; w < 16; w++){ wpref[w] = acc; acc += __popc(keptw[w]); }
    }
    __syncthreads();

    if (tid < KPERF){
        int w = tid >> 5, b2 = tid & 31;
        if ((keptw[w] >> b2) & 1u){
            int rank = wpref[w] + __popc(keptw[w] & ((1u << b2) - 1u));
            if (rank < KEEPC){
                g_fval [t*KEEPC + rank] = svals[tid];
                g_fflat[t*KEEPC + rank] = clsr*KPERF + tid;
                g_faidx[t*KEEPC + rank] = saidx[tid];
            }
        }
    }
    if (tid < KEEPC && tid >= kc) g_fval[t*KEEPC + tid] = -1.0f;
}

// ---------------------------------------------------------------- final binning helpers
__device__ __forceinline__ int bin1(float v){
    float t = (v - 0.99f)*409600.0f;
    int b = (int)t;
    return b < 0 ? 0 : (b > 4095 ? 4095 : b);
}
__device__ __forceinline__ int bin2(float v, int c1){
    if (c1 > 0){
        float t = (v - 0.99f)*409600.0f - (float)c1;
        int s = (int)(t*4096.0f);
        return s < 0 ? 0 : (s > 4095 ? 4095 : s);
    } else {
        int s = (int)(v*4096.0f);
        return s < 0 ? 0 : (s > 4095 ? 4095 : s);
    }
}

// ================================================================ final: per-image global top-100 + gather
__global__ __launch_bounds__(512) void final_kernel(const float* __restrict__ y_pred,
                                                    const float* __restrict__ bbox,
                                                    const float* __restrict__ anch,
                                                    float* __restrict__ out){
    __shared__ int hist[4096];
    __shared__ int wt[16];
    __shared__ int sc, sab, sbin, sc2, scnt;
    __shared__ u64 skey[1024];
    __shared__ int sA[KPROP];
    int tid = threadIdx.x;
    int lane = tid & 31, wrp = tid >> 5;
    int b = blockIdx.x;
    const int gbase = b*MFIN;
    const float4* bbox4 = reinterpret_cast<const float4*>(bbox);
    const float4* anch4 = reinterpret_cast<const float4*>(anch);

    float vreg[RPT];
    #pragma unroll
    for (int k = 0; k < RPT; k++){
        int idx = tid + k*512;
        vreg[k] = (idx < MFIN) ? g_fval[gbase + idx] : -1.0f;
    }

    for (int i = tid; i < 4096; i += 512) hist[i] = 0;
    __syncthreads();
    #pragma unroll
    for (int k = 0; k < RPT; k++){
        float v = vreg[k];
        if (v > 0.f) atomicAdd(&hist[bin1(v)], 1);
    }
    __syncthreads();

    {
        int p = 0;
        #pragma unroll
        for (int k = 0; k < 8; k++) p += hist[tid*8 + k];
        int s = p;
        #pragma unroll
        for (int off = 1; off < 32; off <<= 1){
            int v = __shfl_down_sync(0xFFFFFFFFu, s, off);
            if (lane + off < 32) s += v;
        }
        if (lane == 0) wt[wrp] = s;
        __syncthreads();
        int wsuf = 0;
        #pragma unroll
        for (int j = 0; j < 16; j++) if (j > wrp) wsuf += wt[j];
        int St = s + wsuf;
        if (tid == 0 && St < KPROP){ sc = 0; sab = 0; sbin = 0; }
        if (St >= KPROP && St - p < KPROP){
            int cum = St - p;
            for (int bn = tid*8 + 7; bn >= tid*8; bn--){
                cum += hist[bn];
                if (cum >= KPROP){ sc = bn; sab = cum - hist[bn]; sbin = hist[bn]; break; }
            }
        }
        __syncthreads();
    }
    int c1 = sc, ab1 = sab;
    int c2 = 0;
    bool need2 = (ab1 + sbin > 512);

    if (need2){
        for (int i = tid; i < 4096; i += 512) hist[i] = 0;
        __syncthreads();
        #pragma unroll
        for (int k = 0; k < RPT; k++){
            float v = vreg[k];
            if (v > 0.f && bin1(v) == c1) atomicAdd(&hist[bin2(v, c1)], 1);
        }
        __syncthreads();
        int K2 = KPROP - ab1;
        int p = 0;
        #pragma unroll
        for (int k = 0; k < 8; k++) p += hist[tid*8 + k];
        int s = p;
        #pragma unroll
        for (int off = 1; off < 32; off <<= 1){
            int v = __shfl_down_sync(0xFFFFFFFFu, s, off);
            if (lane + off < 32) s += v;
        }
        if (lane == 0) wt[wrp] = s;
        __syncthreads();
        int wsuf = 0;
        #pragma unroll
        for (int j = 0; j < 16; j++) if (j > wrp) wsuf += wt[j];
        int St = s + wsuf;
        if (tid == 0 && St < K2) sc2 = 0;
        if (St >= K2 && St - p < K2){
            int cum = St - p;
            for (int bn = tid*8 + 7; bn >= tid*8; bn--){
                cum += hist[bn];
                if (cum >= K2){ sc2 = bn; break; }
            }
        }
        __syncthreads();
        c2 = sc2;
    }

    if (tid == 0) scnt = 0;
    __syncthreads();
    #pragma unroll
    for (int k = 0; k < RPT; k++){
        float v = vreg[k];
        if (v > 0.f){
            int bn = bin1(v);
            bool sel = bn > c1;
            if (bn == c1) sel = !need2 || (bin2(v, c1) >= c2);
            if (sel){
                int i = tid + k*512;
                int pos = atomicAdd(&scnt, 1);
                if (pos < 512){
                    u32 fflat = (u32)g_fflat[gbase + i];
                    skey[pos] = ((u64)fmono(v) << 32) | ((u64)(65535u - fflat) << 14) | (u64)i;
                }
            }
        }
    }
    __syncthreads();
    int n = min(scnt, 512);
    for (int i = n + tid; i < 1024; i += 512) skey[i] = 0ull;
    __syncthreads();

    {
        u64 e0 = skey[2*tid], e1 = skey[2*tid + 1];
        hybrid_sort_1024(skey, e0, e1);
    }

    if (tid < KPROP){
        u64 key = skey[tid];
        u32 mk = (u32)(key >> 32);
        if (mk > 0x80000000u){
            int slot = (int)(key & 0x3FFFull);
            sA[tid] = g_faidx[gbase + slot];
        } else sA[tid] = -1;
    }
    __syncthreads();

    float* oscores = out;                         // [B,PROP,C]
    float* oboxes  = out + NB*KPROP*NC;           // [B,PROP,4]
    #pragma unroll
    for (int k = 0; k < 16; k++){
        int idx = tid + k*512;
        if (idx < KPROP*NC){
            int p = idx / NC, cc = idx % NC;
            int a = sA[p];
            oscores[(b*KPROP + p)*NC + cc] = (a >= 0) ? y_pred[((size_t)b*NA + a)*NC + cc] : 0.f;
        }
    }
    if (tid < KPROP){
        int a = sA[tid];
        float4 bx = make_float4(0.f, 0.f, 0.f, 0.f);
        if (a >= 0) bx = decode_box(bbox4[(size_t)b*NA + a], anch4[a]);
        reinterpret_cast<float4*>(oboxes)[b*KPROP + tid] = bx;
    }
}

// ----------------------------------------------------------------
extern "C" void kernel_launch(void* const* d_in, const int* in_sizes, int n_in,
                              void* d_out, int out_size){
    (void)in_sizes; (void)n_in; (void)out_size;
    const float* y    = (const float*)d_in[0];   // [B,A,C]
    const float* bbox = (const float*)d_in[1];   // [B,A,4]
    const float* anch = (const float*)d_in[2];   // [A,4]
    float* out = (float*)d_out;

    collect_kernel<<<dim3(NFULL, NB), 128>>>(y);     // 1
    nms_kernel<<<NTASK, 1024>>>(y, bbox, anch);      // 2
    final_kernel<<<NB, 512>>>(y, bbox, anch, out);   // 3
    // profiled slot 4 = collect_kernel of iteration 2
}